// round 1
// baseline (speedup 1.0000x reference)
#include <cuda_runtime.h>
#include <math.h>

// Problem constants (fixed by the dataset)
#define N_NODES   8192
#define N_EDGES   262144
#define BS_NODES  4096
#define N_SEND    2048
#define KSEG      8          // number of segments (K)
#define ZSTRIDE   18         // 2 * (K+1)

#define TI        1024       // senders staged per smem chunk
#define INT_BLOCKS 256       // 8 segments * 32 j-tiles
#define FLT_BLOCKS 256

__device__ float g_int_part[INT_BLOCKS];
__device__ float g_flt_part[FLT_BLOCKS];
__device__ float g_prior;

// ---------------------------------------------------------------------------
// Integral kernel: for each segment k, sum over (i in senders_unique) x (j in
// all nodes) of the truncated-Gaussian integral term. Each block handles one
// (segment, 256-wide j tile); each thread owns one j and loops over all i.
// Sender params staged through shared memory in 1024-i chunks.
// ---------------------------------------------------------------------------
__global__ void __launch_bounds__(256)
integral_kernel(const float* __restrict__ Z,
                const int*   __restrict__ su,
                const float* __restrict__ cp)
{
    const int blk = blockIdx.x;          // 0..255
    const int k   = blk >> 5;            // segment index 0..7
    const int jt  = blk & 31;            // j tile 0..31
    const int tid = threadIdx.x;
    const int j   = jt * 256 + tid;

    // Receiver-side params (registers)
    const float* zr = Z + j * ZSTRIDE;
    const float r0  = zr[k];
    const float rn0 = zr[k + 1];
    const float r1  = zr[9 + k];
    const float rn1 = zr[9 + k + 1];
    const float dr0 = __fsub_rn(rn0, r0);
    const float dr1 = __fsub_rn(rn1, r1);
    const float rr  = __fadd_rn(__fmul_rn(r0, r0),  __fmul_rn(r1, r1));
    const float drr = __fadd_rn(__fmul_rn(dr0, dr0), __fmul_rn(dr1, dr1));
    const float drz = __fadd_rn(__fmul_rn(dr0, r0),  __fmul_rn(dr1, r1));

    __shared__ float sA0[TI], sA1[TI], sD0[TI], sD1[TI];
    __shared__ float sSS[TI], sDD[TI], sDZ[TI];
    __shared__ float red[256];

    float acc0 = 0.0f, acc1 = 0.0f;

    for (int chunk = 0; chunk < N_SEND; chunk += TI) {
        __syncthreads();
        // Stage sender params for this chunk
        for (int ii = tid; ii < TI; ii += 256) {
            const int s = su[chunk + ii];
            const float* zs = Z + s * ZSTRIDE;
            const float a0 = zs[k];
            const float b0 = zs[k + 1];
            const float a1 = zs[9 + k];
            const float b1 = zs[9 + k + 1];
            const float d0 = __fsub_rn(b0, a0);
            const float d1 = __fsub_rn(b1, a1);
            sA0[ii] = a0; sA1[ii] = a1; sD0[ii] = d0; sD1[ii] = d1;
            sSS[ii] = __fadd_rn(__fmul_rn(a0, a0), __fmul_rn(a1, a1));
            sDD[ii] = __fadd_rn(__fmul_rn(d0, d0), __fmul_rn(d1, d1));
            sDZ[ii] = __fadd_rn(__fmul_rn(d0, a0), __fmul_rn(d1, a1));
        }
        __syncthreads();

        #pragma unroll 4
        for (int i = 0; i < TI; i++) {
            const float a0 = sA0[i], a1 = sA1[i];
            const float d0 = sD0[i], d1 = sD1[i];
            const float ss = sSS[i], dss = sDD[i], dsz = sDZ[i];

            // Dot products with explicit mul/add (no FMA) so that the
            // diagonal (identical sender/receiver) cancels to exactly 0,
            // matching the reference mask semantics.
            const float aa = __fadd_rn(__fmul_rn(a0, r0),  __fmul_rn(a1, r1));
            const float dd = __fadd_rn(__fmul_rn(d0, dr0), __fmul_rn(d1, dr1));
            const float c1 = __fadd_rn(__fmul_rn(d0, r0),  __fmul_rn(d1, r1));
            const float c2 = __fadd_rn(__fmul_rn(a0, dr0), __fmul_rn(a1, dr1));

            const float D = __fadd_rn(__fadd_rn(ss,  rr),  __fmul_rn(-2.0f, aa));
            const float S = __fadd_rn(__fadd_rn(dss, drr), __fmul_rn(-2.0f, dd));
            const float C = __fsub_rn(__fsub_rn(__fadd_rn(c1, c2), dsz), drz);

            const bool mask = (D > 0.0f) && (S > 0.0f);
            const float Ss  = mask ? S : 1.0f;

            const float mu    = __fdividef(C, Ss);
            const float rs    = rsqrtf(Ss);
            const float sqrtS = Ss * rs;               // sqrt(Ss)
            const float sigma = 0.7071067811865476f * rs; // sqrt(0.5/Ss)
            const float e     = Ss * mu * mu - D;
            // cdf((1-mu)/sigma) - cdf(-mu/sigma) = 0.5*(erf((1-mu)*sqrtS) + erf(mu*sqrtS))
            const float cdfd  = 0.5f * (erff((1.0f - mu) * sqrtS) + erff(mu * sqrtS));
            const float val   = __expf(e) * sigma * cdfd;

            const float contrib = mask ? val : 0.0f;
            if (i & 1) acc1 += contrib; else acc0 += contrib;
        }
    }

    const float dt = __fsub_rn(cp[k + 1], cp[k]);
    float tot = (acc0 + acc1) * dt;

    // Deterministic block reduction
    red[tid] = tot;
    __syncthreads();
    for (int s = 128; s > 0; s >>= 1) {
        if (tid < s) red[tid] += red[tid + s];
        __syncthreads();
    }
    if (tid == 0) g_int_part[blk] = red[0];
}

// ---------------------------------------------------------------------------
// flt kernel: per-edge interpolated similarity term
// ---------------------------------------------------------------------------
__global__ void __launch_bounds__(256)
flt_kernel(const float* __restrict__ Z,
           const float* __restrict__ ts,
           const int*   __restrict__ snd,
           const int*   __restrict__ rcv,
           const float* __restrict__ cp)
{
    const int tid     = threadIdx.x;
    const int gthread = blockIdx.x * 256 + tid;
    const int nthread = FLT_BLOCKS * 256;
    const float seg   = __fsub_rn(cp[1], cp[0]);

    float acc = 0.0f;
    for (int e = gthread; e < N_EDGES; e += nthread) {
        const float t  = ts[e];
        const float q  = t / seg;           // IEEE divide, matches reference
        const float kf = floorf(q);
        const int   ka = (int)kf;
        const float d  = q - kf;
        const float od = 1.0f - d;

        const float* zs = Z + snd[e] * ZSTRIDE;
        const float* zr = Z + rcv[e] * ZSTRIDE;
        const float sc0 = zs[ka],     sn0 = zs[ka + 1];
        const float sc1 = zs[9 + ka], sn1 = zs[9 + ka + 1];
        const float rc0 = zr[ka],     rn0 = zr[ka + 1];
        const float rc1 = zr[9 + ka], rn1 = zr[9 + ka + 1];

        const float scrc = sc0 * rc0 + sc1 * rc1;
        const float scsc = sc0 * sc0 + sc1 * sc1;
        const float rcrc = rc0 * rc0 + rc1 * rc1;
        const float scrn = sc0 * rn0 + sc1 * rn1;
        const float snrc = sn0 * rc0 + sn1 * rc1;
        const float scsn = sc0 * sn0 + sc1 * sn1;
        const float rcrn = rc0 * rn0 + rc1 * rn1;
        const float snrn = sn0 * rn0 + sn1 * rn1;
        const float snsn = sn0 * sn0 + sn1 * sn1;
        const float rnrn = rn0 * rn0 + rn1 * rn1;

        const float flt = od * od * (2.0f * scrc - scsc - rcrc)
                        + 2.0f * d * od * (scrn + snrc - scsn - rcrn)
                        + d * d * (2.0f * snrn - snsn - rnrn);
        acc += flt;
    }

    __shared__ float red[256];
    red[tid] = acc;
    __syncthreads();
    for (int s = 128; s > 0; s >>= 1) {
        if (tid < s) red[tid] += red[tid + s];
        __syncthreads();
    }
    if (tid == 0) g_flt_part[blockIdx.x] = red[0];
}

// ---------------------------------------------------------------------------
// prior kernel: gauss-markov prior over sampled nodes (1 block)
// ---------------------------------------------------------------------------
__global__ void __launch_bounds__(256)
prior_kernel(const float* __restrict__ Z, const int* __restrict__ nodes)
{
    const int tid = threadIdx.x;
    float acc = 0.0f;
    for (int m = tid; m < BS_NODES; m += 256) {
        const int n = nodes[m];
        const float* z = Z + n * ZSTRIDE;
        #pragma unroll
        for (int dim = 0; dim < 2; dim++) {
            const float* zd = z + dim * 9;
            float prev = zd[0];
            acc += prev * prev;
            #pragma unroll
            for (int kk = 1; kk <= KSEG; kk++) {
                const float cur = zd[kk];
                const float df  = cur - prev;
                acc += df * df;
                prev = cur;
            }
        }
    }
    __shared__ float red[256];
    red[tid] = acc;
    __syncthreads();
    for (int s = 128; s > 0; s >>= 1) {
        if (tid < s) red[tid] += red[tid + s];
        __syncthreads();
    }
    if (tid == 0) g_prior = red[0];
}

// ---------------------------------------------------------------------------
// Final combine (deterministic fixed-order reduction)
// ---------------------------------------------------------------------------
__global__ void final_kernel(const float* __restrict__ beta_p,
                             float* __restrict__ out)
{
    float integral = 0.0f;
    for (int i = 0; i < INT_BLOCKS; i++) integral += g_int_part[i];
    float flt = 0.0f;
    for (int i = 0; i < FLT_BLOCKS; i++) flt += g_flt_part[i];

    const float beta     = beta_p[0];
    const float prior    = 10.0f * g_prior;                  // PENALTY
    const float n_entr   = 262144.0f;
    const float sqrt2pi  = sqrtf(6.283185307179586f);
    const float result   = 2.0f * (prior - beta * n_entr - flt
                                   + sqrt2pi * expf(beta) * (0.5f * integral));
    out[0] = result;
}

// ---------------------------------------------------------------------------
extern "C" void kernel_launch(void* const* d_in, const int* in_sizes, int n_in,
                              void* d_out, int out_size)
{
    const float* Z    = (const float*)d_in[0];
    const float* beta = (const float*)d_in[1];
    const float* ts   = (const float*)d_in[2];
    const int*   snd  = (const int*)d_in[3];
    const int*   rcv  = (const int*)d_in[4];
    const int*   nds  = (const int*)d_in[5];
    const int*   su   = (const int*)d_in[6];
    const float* cp   = (const float*)d_in[7];
    float* out = (float*)d_out;

    prior_kernel<<<1, 256>>>(Z, nds);
    flt_kernel<<<FLT_BLOCKS, 256>>>(Z, ts, snd, rcv, cp);
    integral_kernel<<<INT_BLOCKS, 256>>>(Z, su, cp);
    final_kernel<<<1, 1>>>(beta, out);
}

// round 3
// speedup vs baseline: 1.3746x; 1.3746x over previous
#include <cuda_runtime.h>
#include <math.h>

// Problem constants (fixed by the dataset)
#define N_NODES   8192
#define N_EDGES   262144
#define BS_NODES  4096
#define N_SEND    2048
#define ZSTRIDE   18         // 2 * (K+1)

#define IC        256        // senders staged per unit
#define N_UNITS   2048       // 8 seg * 32 j-tiles * 8 i-chunks
#define INT_GRID  592        // 4 * 148 SMs; dynamic stealing absorbs occupancy
#define FLT_BLOCKS 256

__device__ float g_int_part[N_UNITS];
__device__ float g_flt_part[FLT_BLOCKS];
__device__ float g_prior;
__device__ unsigned int g_unit_ctr = 0;

// ---------------------------------------------------------------------------
// Packed fp32 (f32x2) helpers — FFMA2/FADD2/FMUL2 on sm_103a via PTX
// ---------------------------------------------------------------------------
typedef unsigned long long u64_t;
union F2U { float2 f; u64_t u; };

__device__ __forceinline__ u64_t f2u(float2 v) { F2U x; x.f = v; return x.u; }
__device__ __forceinline__ float2 u2f(u64_t v) { F2U x; x.u = v; return x.f; }

__device__ __forceinline__ float2 mul2(float2 a, float2 b) {
    u64_t d;
    asm("mul.rn.f32x2 %0, %1, %2;" : "=l"(d) : "l"(f2u(a)), "l"(f2u(b)));
    return u2f(d);
}
__device__ __forceinline__ float2 add2(float2 a, float2 b) {
    u64_t d;
    asm("add.rn.f32x2 %0, %1, %2;" : "=l"(d) : "l"(f2u(a)), "l"(f2u(b)));
    return u2f(d);
}
__device__ __forceinline__ float2 fma2(float2 a, float2 b, float2 c) {
    u64_t d;
    asm("fma.rn.f32x2 %0, %1, %2, %3;"
        : "=l"(d) : "l"(f2u(a)), "l"(f2u(b)), "l"(f2u(c)));
    return u2f(d);
}
__device__ __forceinline__ float2 neg2(float2 a) {
    F2U x; x.f = a; x.u ^= 0x8000000080000000ULL; return x.f;
}
__device__ __forceinline__ float2 sub2(float2 a, float2 b) { return add2(a, neg2(b)); }
__device__ __forceinline__ float2 splat2(float v) { return make_float2(v, v); }

__device__ __forceinline__ float fast_rsqrt(float x) {
    float r; asm("rsqrt.approx.f32 %0, %1;" : "=f"(r) : "f"(x)); return r;
}
__device__ __forceinline__ float fast_ex2(float x) {
    float r; asm("ex2.approx.f32 %0, %1;" : "=f"(r) : "f"(x)); return r;
}

// ---------------------------------------------------------------------------
// Branchless packed erf (njuffa-style two-path, ~2.4 ulp), both paths computed
// and selected per half so the whole thing vectorizes in f32x2.
// ---------------------------------------------------------------------------
__device__ __forceinline__ float2 erf2(float2 x) {
    // small path: |x| <= 0.921875 : x * P(x^2) + x
    float2 s = mul2(x, x);
    float2 p = fma2(splat2(-5.96761703e-4f), s, splat2( 4.99119423e-3f));
    p = fma2(p, s, splat2(-2.67681349e-2f));
    p = fma2(p, s, splat2( 1.12819925e-1f));
    p = fma2(p, s, splat2(-3.76125336e-1f));
    p = fma2(p, s, splat2( 1.28379166e-1f));
    float2 sm = fma2(p, x, x);

    // large path: |x| > 0.921875 : 1 - exp(Q(|x|))
    F2U ax; ax.f = x; ax.u &= 0x7FFFFFFF7FFFFFFFULL;
    float2 t = ax.f;
    float2 q = fma2(splat2(-1.72853470e-5f), t, splat2( 3.83197126e-4f));
    q = fma2(q, t, splat2(-3.88396438e-3f));
    q = fma2(q, t, splat2( 2.42546219e-2f));
    q = fma2(q, t, splat2(-1.06777877e-1f));
    q = fma2(q, t, splat2(-6.34846687e-1f));
    q = fma2(q, t, splat2(-1.28717512e-1f));
    q = fma2(q, t, neg2(t));
    float2 qa = mul2(q, splat2(1.4426950408889634f));
    float2 eq;
    eq.x = fast_ex2(qa.x);
    eq.y = fast_ex2(qa.y);
    float2 lg = sub2(splat2(1.0f), eq);

    float2 r;
    r.x = (t.x > 0.921875f) ? copysignf(lg.x, x.x) : sm.x;
    r.y = (t.y > 0.921875f) ? copysignf(lg.y, x.y) : sm.y;
    return r;
}

// ---------------------------------------------------------------------------
// Integral kernel: dynamic work-stealing over 2048 units.
// Unit = (segment k, j-tile of 256 nodes, i-chunk of 256 senders).
// Thread owns one j; inner loop is f32x2 over sender pairs.
// ---------------------------------------------------------------------------
__global__ void __launch_bounds__(256)
integral_kernel(const float* __restrict__ Z,
                const int*   __restrict__ su,
                const float* __restrict__ cp)
{
    __shared__ __align__(16) float sA0[IC], sA1[IC], sD0[IC], sD1[IC];
    __shared__ __align__(16) float sSS[IC], sDD[IC], sNDZ[IC];
    __shared__ float red[256];
    __shared__ int s_unit;

    const int tid = threadIdx.x;

    for (;;) {
        __syncthreads();
        if (tid == 0) s_unit = (int)atomicAdd(&g_unit_ctr, 1u);
        __syncthreads();
        const int u = s_unit;
        if (u >= N_UNITS) break;

        const int k   = u >> 8;        // 0..7
        const int rem = u & 255;
        const int jt  = rem >> 3;      // 0..31
        const int ic  = rem & 7;       // 0..7

        // Receiver params (register, splatted to both f32x2 halves)
        const int j = jt * 256 + tid;
        const float* zr = Z + j * ZSTRIDE;
        const float r0  = zr[k];
        const float rn0 = zr[k + 1];
        const float r1  = zr[9 + k];
        const float rn1 = zr[9 + k + 1];
        const float dr0 = rn0 - r0;
        const float dr1 = rn1 - r1;
        const float rr   = __fmaf_rn(r1, r1, __fmul_rn(r0, r0));
        const float drr  = __fmaf_rn(dr1, dr1, __fmul_rn(dr0, dr0));
        const float ndrz = -__fmaf_rn(dr1, r1, __fmul_rn(dr0, r0));
        const float2 R0 = splat2(r0),  R1 = splat2(r1);
        const float2 DR0 = splat2(dr0), DR1 = splat2(dr1);
        const float2 RR = splat2(rr),  DRR = splat2(drr), NDRZ = splat2(ndrz);

        // Stage 256 senders (one per thread)
        {
            const int sidx = su[ic * IC + tid];
            const float* zs = Z + sidx * ZSTRIDE;
            const float a0 = zs[k];
            const float b0 = zs[k + 1];
            const float a1 = zs[9 + k];
            const float b1 = zs[9 + k + 1];
            const float d0 = b0 - a0;
            const float d1 = b1 - a1;
            sA0[tid] = a0; sA1[tid] = a1; sD0[tid] = d0; sD1[tid] = d1;
            // EXACTLY the same op sequence as aa/dd below so the diagonal
            // (sender node == receiver node) cancels to exactly 0.
            sSS[tid]  = __fmaf_rn(a1, a1, __fmul_rn(a0, a0));
            sDD[tid]  = __fmaf_rn(d1, d1, __fmul_rn(d0, d0));
            sNDZ[tid] = -__fmaf_rn(d1, a1, __fmul_rn(d0, a0));
        }
        __syncthreads();

        float2 acc = splat2(0.0f);
        #pragma unroll 4
        for (int i = 0; i < IC; i += 2) {
            const float2 A0  = *(const float2*)&sA0[i];
            const float2 A1  = *(const float2*)&sA1[i];
            const float2 D0  = *(const float2*)&sD0[i];
            const float2 D1  = *(const float2*)&sD1[i];
            const float2 SS  = *(const float2*)&sSS[i];
            const float2 DDs = *(const float2*)&sDD[i];
            const float2 NDZ = *(const float2*)&sNDZ[i];

            const float2 aa = fma2(A1, R1,  mul2(A0, R0));
            const float2 dd = fma2(D1, DR1, mul2(D0, DR0));
            const float2 c1 = fma2(D1, R1,  mul2(D0, R0));
            const float2 c2 = fma2(A1, DR1, mul2(A0, DR0));

            const float2 Dv = add2(sub2(SS,  aa), sub2(RR,  aa));
            const float2 Sv = add2(sub2(DDs, dd), sub2(DRR, dd));
            const float2 Cv = add2(add2(c1, c2), add2(NDZ, NDRZ));

            float2 Ss2;
            Ss2.x = fmaxf(Sv.x, 1e-30f);
            Ss2.y = fmaxf(Sv.y, 1e-30f);
            float2 irs;
            irs.x = fast_rsqrt(Ss2.x);
            irs.y = fast_rsqrt(Ss2.y);

            const float2 sq  = mul2(Ss2, irs);          // sqrt(Ss)
            const float2 cir = mul2(Cv, irs);           // mu*sqrt(S)
            const float2 x1  = sub2(sq, cir);           // (1-mu)*sqrt(S)
            const float2 e   = fma2(cir, cir, neg2(Dv));// S*mu^2 - D
            const float2 ea  = mul2(e, splat2(1.4426950408889634f));
            float2 ex;
            ex.x = fast_ex2(ea.x);
            ex.y = fast_ex2(ea.y);

            const float2 es = add2(erf2(x1), erf2(cir));
            const float2 v  = mul2(mul2(ex, es), irs);

            float2 contrib;
            contrib.x = (Dv.x > 0.0f && Sv.x > 0.0f) ? v.x : 0.0f;
            contrib.y = (Dv.y > 0.0f && Sv.y > 0.0f) ? v.y : 0.0f;
            acc = add2(acc, contrib);
        }

        const float dt = cp[k + 1] - cp[k];
        // fold sigma's 1/sqrt(2), the cdf 0.5 and the scan 0.5: 0.25/sqrt(2)
        const float tot = (acc.x + acc.y) * (dt * 0.17677669529663687f);

        red[tid] = tot;
        __syncthreads();
        for (int s2 = 128; s2 > 0; s2 >>= 1) {
            if (tid < s2) red[tid] += red[tid + s2];
            __syncthreads();
        }
        if (tid == 0) g_int_part[u] = red[0];
    }
}

// ---------------------------------------------------------------------------
// flt kernel: per-edge interpolated similarity term
// ---------------------------------------------------------------------------
__global__ void __launch_bounds__(256)
flt_kernel(const float* __restrict__ Z,
           const float* __restrict__ ts,
           const int*   __restrict__ snd,
           const int*   __restrict__ rcv,
           const float* __restrict__ cp)
{
    const int tid     = threadIdx.x;
    const int gthread = blockIdx.x * 256 + tid;
    const int nthread = FLT_BLOCKS * 256;
    const float seg   = cp[1] - cp[0];

    float acc = 0.0f;
    for (int e = gthread; e < N_EDGES; e += nthread) {
        const float t  = ts[e];
        const float q  = t / seg;
        const float kf = floorf(q);
        const int   ka = (int)kf;
        const float d  = q - kf;
        const float od = 1.0f - d;

        const float* zs = Z + snd[e] * ZSTRIDE;
        const float* zr = Z + rcv[e] * ZSTRIDE;
        const float sc0 = zs[ka],     sn0 = zs[ka + 1];
        const float sc1 = zs[9 + ka], sn1 = zs[9 + ka + 1];
        const float rc0 = zr[ka],     rn0 = zr[ka + 1];
        const float rc1 = zr[9 + ka], rn1 = zr[9 + ka + 1];

        const float scrc = sc0 * rc0 + sc1 * rc1;
        const float scsc = sc0 * sc0 + sc1 * sc1;
        const float rcrc = rc0 * rc0 + rc1 * rc1;
        const float scrn = sc0 * rn0 + sc1 * rn1;
        const float snrc = sn0 * rc0 + sn1 * rc1;
        const float scsn = sc0 * sn0 + sc1 * sn1;
        const float rcrn = rc0 * rn0 + rc1 * rn1;
        const float snrn = sn0 * rn0 + sn1 * rn1;
        const float snsn = sn0 * sn0 + sn1 * sn1;
        const float rnrn = rn0 * rn0 + rn1 * rn1;

        const float flt = od * od * (2.0f * scrc - scsc - rcrc)
                        + 2.0f * d * od * (scrn + snrc - scsn - rcrn)
                        + d * d * (2.0f * snrn - snsn - rnrn);
        acc += flt;
    }

    __shared__ float red[256];
    red[tid] = acc;
    __syncthreads();
    for (int s = 128; s > 0; s >>= 1) {
        if (tid < s) red[tid] += red[tid + s];
        __syncthreads();
    }
    if (tid == 0) g_flt_part[blockIdx.x] = red[0];
}

// ---------------------------------------------------------------------------
// prior kernel: gauss-markov prior over sampled nodes (1 block)
// ---------------------------------------------------------------------------
__global__ void __launch_bounds__(256)
prior_kernel(const float* __restrict__ Z, const int* __restrict__ nodes)
{
    const int tid = threadIdx.x;
    float acc = 0.0f;
    for (int m = tid; m < BS_NODES; m += 256) {
        const int n = nodes[m];
        const float* z = Z + n * ZSTRIDE;
        #pragma unroll
        for (int dim = 0; dim < 2; dim++) {
            const float* zd = z + dim * 9;
            float prev = zd[0];
            acc += prev * prev;
            #pragma unroll
            for (int kk = 1; kk <= 8; kk++) {
                const float cur = zd[kk];
                const float df  = cur - prev;
                acc += df * df;
                prev = cur;
            }
        }
    }
    __shared__ float red[256];
    red[tid] = acc;
    __syncthreads();
    for (int s = 128; s > 0; s >>= 1) {
        if (tid < s) red[tid] += red[tid + s];
        __syncthreads();
    }
    if (tid == 0) g_prior = red[0];
}

// ---------------------------------------------------------------------------
// Final combine (parallel, deterministic fixed-order reduction) + counter reset
// ---------------------------------------------------------------------------
__global__ void __launch_bounds__(256)
final_kernel(const float* __restrict__ beta_p, float* __restrict__ out)
{
    __shared__ float red[256];
    __shared__ float s_integral;
    const int tid = threadIdx.x;

    float s = 0.0f;
    #pragma unroll
    for (int i = tid; i < N_UNITS; i += 256) s += g_int_part[i];
    red[tid] = s;
    __syncthreads();
    for (int st = 128; st > 0; st >>= 1) {
        if (tid < st) red[tid] += red[tid + st];
        __syncthreads();
    }
    if (tid == 0) s_integral = red[0];
    __syncthreads();

    red[tid] = g_flt_part[tid];
    __syncthreads();
    for (int st = 128; st > 0; st >>= 1) {
        if (tid < st) red[tid] += red[tid + st];
        __syncthreads();
    }

    if (tid == 0) {
        const float flt      = red[0];
        const float integral = s_integral;
        const float beta     = beta_p[0];
        const float prior    = 10.0f * g_prior;              // PENALTY
        const float result   = 2.0f * (prior - beta * 262144.0f - flt
                                + 2.5066282746310002f * expf(beta) * integral);
        out[0] = result;
        g_unit_ctr = 0;   // reset work-stealing counter for the next call
    }
}

// ---------------------------------------------------------------------------
extern "C" void kernel_launch(void* const* d_in, const int* in_sizes, int n_in,
                              void* d_out, int out_size)
{
    const float* Z    = (const float*)d_in[0];
    const float* beta = (const float*)d_in[1];
    const float* ts   = (const float*)d_in[2];
    const int*   snd  = (const int*)d_in[3];
    const int*   rcv  = (const int*)d_in[4];
    const int*   nds  = (const int*)d_in[5];
    const int*   su   = (const int*)d_in[6];
    const float* cp   = (const float*)d_in[7];
    float* out = (float*)d_out;

    // integral placed 2nd so ncu's fixed "-s 5 -c 1" (6th launch = 2nd kernel
    // of the 2nd replay) lands on it.
    prior_kernel<<<1, 256>>>(Z, nds);
    integral_kernel<<<INT_GRID, 256>>>(Z, su, cp);
    flt_kernel<<<FLT_BLOCKS, 256>>>(Z, ts, snd, rcv, cp);
    final_kernel<<<1, 256>>>(beta, out);
}

// round 4
// speedup vs baseline: 1.7474x; 1.2712x over previous
#include <cuda_runtime.h>
#include <math.h>

// Problem constants (fixed by the dataset)
#define N_NODES   8192
#define N_EDGES   262144
#define BS_NODES  4096
#define N_SEND    2048
#define ZSTRIDE   18         // 2 * (K+1)

#define IC        256        // senders staged per unit
#define N_UNITS   2048       // 8 seg * 32 j-tiles * 8 i-chunks
#define INT_GRID  592        // 4 * 148 SMs; dynamic stealing absorbs imbalance
#define FLT_BLOCKS 256

__device__ float g_int_part[N_UNITS];
__device__ float g_flt_part[FLT_BLOCKS];
__device__ float g_prior;
__device__ unsigned int g_unit_ctr = 0;

// ---------------------------------------------------------------------------
// Packed fp32 (f32x2) helpers — FFMA2/FADD2/FMUL2 on sm_103a via PTX
// ---------------------------------------------------------------------------
typedef unsigned long long u64_t;
union F2U { float2 f; u64_t u; };

__device__ __forceinline__ u64_t f2u(float2 v) { F2U x; x.f = v; return x.u; }
__device__ __forceinline__ float2 u2f(u64_t v) { F2U x; x.u = v; return x.f; }

__device__ __forceinline__ float2 mul2(float2 a, float2 b) {
    u64_t d;
    asm("mul.rn.f32x2 %0, %1, %2;" : "=l"(d) : "l"(f2u(a)), "l"(f2u(b)));
    return u2f(d);
}
__device__ __forceinline__ float2 add2(float2 a, float2 b) {
    u64_t d;
    asm("add.rn.f32x2 %0, %1, %2;" : "=l"(d) : "l"(f2u(a)), "l"(f2u(b)));
    return u2f(d);
}
__device__ __forceinline__ float2 fma2(float2 a, float2 b, float2 c) {
    u64_t d;
    asm("fma.rn.f32x2 %0, %1, %2, %3;"
        : "=l"(d) : "l"(f2u(a)), "l"(f2u(b)), "l"(f2u(c)));
    return u2f(d);
}
__device__ __forceinline__ float2 neg2(float2 a) {
    F2U x; x.f = a; x.u ^= 0x8000000080000000ULL; return x.f;
}
__device__ __forceinline__ float2 abs2(float2 a) {
    F2U x; x.f = a; x.u &= 0x7FFFFFFF7FFFFFFFULL; return x.f;
}
__device__ __forceinline__ float2 sub2(float2 a, float2 b) { return add2(a, neg2(b)); }
__device__ __forceinline__ float2 splat2(float v) { return make_float2(v, v); }

__device__ __forceinline__ float fast_rsqrt(float x) {
    float r; asm("rsqrt.approx.f32 %0, %1;" : "=f"(r) : "f"(x)); return r;
}
__device__ __forceinline__ float fast_ex2(float x) {
    float r; asm("ex2.approx.f32 %0, %1;" : "=f"(r) : "f"(x)); return r;
}
__device__ __forceinline__ float fast_rcp(float x) {
    float r; asm("rcp.approx.f32 %0, %1;" : "=f"(r) : "f"(x)); return r;
}

// ---------------------------------------------------------------------------
// Integral kernel: dynamic work-stealing over 2048 units.
// Unit = (segment k, j-tile of 256 nodes, i-chunk of 256 senders).
// Thread owns one j; inner loop is f32x2 over sender pairs.
//
// Identities used (w = Zs0 - Zr0, v = DZs - DZr):
//   D = |w|^2, S = |v|^2, C = -(v . w)
// so the diagonal (sender == receiver) gives exactly D = S = 0 -> masked,
// and by Cauchy-Schwarz e = S*mu^2 - D = (v.w)^2/|v|^2 - |w|^2 <= 0 (no
// exp overflow).
// erf via Abramowitz-Stegun 7.1.26 (|err| < 1.5e-7), the two reciprocals
// fused through a single rcp.
// ---------------------------------------------------------------------------
__global__ void __launch_bounds__(256)
integral_kernel(const float* __restrict__ Z,
                const int*   __restrict__ su,
                const float* __restrict__ cp)
{
    __shared__ __align__(16) float sA0[IC], sA1[IC], sD0[IC], sD1[IC];
    __shared__ float red[256];
    __shared__ int s_unit;

    const int tid = threadIdx.x;

    const float2 ONE  = splat2(1.0f);
    const float2 L2E  = splat2( 1.4426950408889634f);
    const float2 NL2E = splat2(-1.4426950408889634f);
    const float2 PP   = splat2(0.3275911f);
    // negated A&S coefficients (so erf = 1 + poly(t)*exp(-x^2))
    const float2 C5 = splat2(-1.061405429f);
    const float2 C4 = splat2( 1.453152027f);
    const float2 C3 = splat2(-1.421413741f);
    const float2 C2 = splat2( 0.284496736f);
    const float2 C1 = splat2(-0.254829592f);

    for (;;) {
        __syncthreads();
        if (tid == 0) s_unit = (int)atomicAdd(&g_unit_ctr, 1u);
        __syncthreads();
        const int u = s_unit;
        if (u >= N_UNITS) break;

        const int k   = u >> 8;        // 0..7
        const int rem = u & 255;
        const int jt  = rem >> 3;      // 0..31
        const int ic  = rem & 7;       // 0..7

        // Receiver params (register, splatted to both f32x2 halves)
        const int j = jt * 256 + tid;
        const float* zr = Z + j * ZSTRIDE;
        const float r0  = zr[k];
        const float rn0 = zr[k + 1];
        const float r1  = zr[9 + k];
        const float rn1 = zr[9 + k + 1];
        const float2 R0  = splat2(r0);
        const float2 R1  = splat2(r1);
        const float2 DR0 = splat2(rn0 - r0);
        const float2 DR1 = splat2(rn1 - r1);

        // Stage 256 senders (one per thread)
        {
            const int sidx = su[ic * IC + tid];
            const float* zs = Z + sidx * ZSTRIDE;
            const float a0 = zs[k];
            const float b0 = zs[k + 1];
            const float a1 = zs[9 + k];
            const float b1 = zs[9 + k + 1];
            sA0[tid] = a0; sA1[tid] = a1;
            sD0[tid] = b0 - a0; sD1[tid] = b1 - a1;
        }
        __syncthreads();

        float2 acc = splat2(0.0f);
        #pragma unroll 4
        for (int i = 0; i < IC; i += 2) {
            const float2 A0  = *(const float2*)&sA0[i];
            const float2 A1  = *(const float2*)&sA1[i];
            const float2 Dz0 = *(const float2*)&sD0[i];
            const float2 Dz1 = *(const float2*)&sD1[i];

            // w = Zs0 - Zr0, v = DZs - DZr (exact 0 on the diagonal)
            const float2 w0 = sub2(A0, R0);
            const float2 w1 = sub2(A1, R1);
            const float2 v0 = sub2(Dz0, DR0);
            const float2 v1 = sub2(Dz1, DR1);

            const float2 Dv = fma2(w1, w1, mul2(w0, w0));
            const float2 Sv = fma2(v1, v1, mul2(v0, v0));
            const float2 nC = fma2(v1, w1, mul2(v0, w0));   // = v.w = -C

            float2 irs;
            irs.x = fast_rsqrt(Sv.x);
            irs.y = fast_rsqrt(Sv.y);

            const float2 sq   = mul2(Sv, irs);              // sqrt(S)
            const float2 ncir = mul2(nC, irs);              // -mu*sqrt(S)
            const float2 x1   = add2(sq, ncir);             // (1-mu)*sqrt(S)
            const float2 e    = fma2(ncir, ncir, neg2(Dv)); // S*mu^2 - D <= 0

            const float2 ea = mul2(e, L2E);
            float2 ex;
            ex.x = fast_ex2(ea.x);
            ex.y = fast_ex2(ea.y);

            // --- fused erf(x1) and erf(ncir), A&S 7.1.26 ---
            const float2 ax1 = abs2(x1);
            const float2 ax2 = abs2(ncir);
            const float2 q1  = fma2(PP, ax1, ONE);
            const float2 q2  = fma2(PP, ax2, ONE);
            const float2 ab  = mul2(q1, q2);
            float2 rr;
            rr.x = fast_rcp(ab.x);
            rr.y = fast_rcp(ab.y);
            const float2 t1 = mul2(q2, rr);                 // 1/q1
            const float2 t2 = mul2(q1, rr);                 // 1/q2

            float2 g1 = fma2(C5, t1, C4);
            g1 = fma2(g1, t1, C3);
            g1 = fma2(g1, t1, C2);
            g1 = fma2(g1, t1, C1);
            g1 = mul2(g1, t1);
            float2 g2 = fma2(C5, t2, C4);
            g2 = fma2(g2, t2, C3);
            g2 = fma2(g2, t2, C2);
            g2 = fma2(g2, t2, C1);
            g2 = mul2(g2, t2);

            const float2 s1a = mul2(mul2(x1, x1), NL2E);
            const float2 s2a = mul2(mul2(ncir, ncir), NL2E);
            float2 E1, E2;
            E1.x = fast_ex2(s1a.x);  E1.y = fast_ex2(s1a.y);
            E2.x = fast_ex2(s2a.x);  E2.y = fast_ex2(s2a.y);

            float2 f1 = fma2(g1, E1, ONE);                  // erf(|x1|)
            float2 f2 = fma2(g2, E2, ONE);                  // erf(|ncir|)
            f1.x = copysignf(f1.x, x1.x);
            f1.y = copysignf(f1.y, x1.y);
            f2.x = copysignf(f2.x, ncir.x);
            f2.y = copysignf(f2.y, ncir.y);

            // erf(x1) + erf(cir) = erf(x1) - erf(ncir)
            const float2 es = sub2(f1, f2);
            const float2 vv = mul2(mul2(ex, es), irs);

            float2 contrib;
            contrib.x = (Dv.x > 0.0f && Sv.x > 0.0f) ? vv.x : 0.0f;
            contrib.y = (Dv.y > 0.0f && Sv.y > 0.0f) ? vv.y : 0.0f;
            acc = add2(acc, contrib);
        }

        const float dt = cp[k + 1] - cp[k];
        // fold sigma's 1/sqrt(2), the cdf 0.5 and the scan 0.5: 0.25/sqrt(2)
        const float tot = (acc.x + acc.y) * (dt * 0.17677669529663687f);

        red[tid] = tot;
        __syncthreads();
        for (int s2 = 128; s2 > 0; s2 >>= 1) {
            if (tid < s2) red[tid] += red[tid + s2];
            __syncthreads();
        }
        if (tid == 0) g_int_part[u] = red[0];
    }
}

// ---------------------------------------------------------------------------
// flt kernel: per-edge interpolated similarity term
// ---------------------------------------------------------------------------
__global__ void __launch_bounds__(256)
flt_kernel(const float* __restrict__ Z,
           const float* __restrict__ ts,
           const int*   __restrict__ snd,
           const int*   __restrict__ rcv,
           const float* __restrict__ cp)
{
    const int tid     = threadIdx.x;
    const int gthread = blockIdx.x * 256 + tid;
    const int nthread = FLT_BLOCKS * 256;
    const float seg   = cp[1] - cp[0];

    float acc = 0.0f;
    for (int e = gthread; e < N_EDGES; e += nthread) {
        const float t  = ts[e];
        const float q  = t / seg;
        const float kf = floorf(q);
        const int   ka = (int)kf;
        const float d  = q - kf;
        const float od = 1.0f - d;

        const float* zs = Z + snd[e] * ZSTRIDE;
        const float* zr = Z + rcv[e] * ZSTRIDE;
        const float sc0 = zs[ka],     sn0 = zs[ka + 1];
        const float sc1 = zs[9 + ka], sn1 = zs[9 + ka + 1];
        const float rc0 = zr[ka],     rn0 = zr[ka + 1];
        const float rc1 = zr[9 + ka], rn1 = zr[9 + ka + 1];

        const float scrc = sc0 * rc0 + sc1 * rc1;
        const float scsc = sc0 * sc0 + sc1 * sc1;
        const float rcrc = rc0 * rc0 + rc1 * rc1;
        const float scrn = sc0 * rn0 + sc1 * rn1;
        const float snrc = sn0 * rc0 + sn1 * rc1;
        const float scsn = sc0 * sn0 + sc1 * sn1;
        const float rcrn = rc0 * rn0 + rc1 * rn1;
        const float snrn = sn0 * rn0 + sn1 * rn1;
        const float snsn = sn0 * sn0 + sn1 * sn1;
        const float rnrn = rn0 * rn0 + rn1 * rn1;

        const float flt = od * od * (2.0f * scrc - scsc - rcrc)
                        + 2.0f * d * od * (scrn + snrc - scsn - rcrn)
                        + d * d * (2.0f * snrn - snsn - rnrn);
        acc += flt;
    }

    __shared__ float red[256];
    red[tid] = acc;
    __syncthreads();
    for (int s = 128; s > 0; s >>= 1) {
        if (tid < s) red[tid] += red[tid + s];
        __syncthreads();
    }
    if (tid == 0) g_flt_part[blockIdx.x] = red[0];
}

// ---------------------------------------------------------------------------
// prior kernel: gauss-markov prior over sampled nodes (1 block)
// ---------------------------------------------------------------------------
__global__ void __launch_bounds__(256)
prior_kernel(const float* __restrict__ Z, const int* __restrict__ nodes)
{
    const int tid = threadIdx.x;
    float acc = 0.0f;
    for (int m = tid; m < BS_NODES; m += 256) {
        const int n = nodes[m];
        const float* z = Z + n * ZSTRIDE;
        #pragma unroll
        for (int dim = 0; dim < 2; dim++) {
            const float* zd = z + dim * 9;
            float prev = zd[0];
            acc += prev * prev;
            #pragma unroll
            for (int kk = 1; kk <= 8; kk++) {
                const float cur = zd[kk];
                const float df  = cur - prev;
                acc += df * df;
                prev = cur;
            }
        }
    }
    __shared__ float red[256];
    red[tid] = acc;
    __syncthreads();
    for (int s = 128; s > 0; s >>= 1) {
        if (tid < s) red[tid] += red[tid + s];
        __syncthreads();
    }
    if (tid == 0) g_prior = red[0];
}

// ---------------------------------------------------------------------------
// Final combine (parallel, deterministic fixed-order reduction) + counter reset
// ---------------------------------------------------------------------------
__global__ void __launch_bounds__(256)
final_kernel(const float* __restrict__ beta_p, float* __restrict__ out)
{
    __shared__ float red[256];
    __shared__ float s_integral;
    const int tid = threadIdx.x;

    float s = 0.0f;
    #pragma unroll
    for (int i = tid; i < N_UNITS; i += 256) s += g_int_part[i];
    red[tid] = s;
    __syncthreads();
    for (int st = 128; st > 0; st >>= 1) {
        if (tid < st) red[tid] += red[tid + st];
        __syncthreads();
    }
    if (tid == 0) s_integral = red[0];
    __syncthreads();

    red[tid] = g_flt_part[tid];
    __syncthreads();
    for (int st = 128; st > 0; st >>= 1) {
        if (tid < st) red[tid] += red[tid + st];
        __syncthreads();
    }

    if (tid == 0) {
        const float flt      = red[0];
        const float integral = s_integral;
        const float beta     = beta_p[0];
        const float prior    = 10.0f * g_prior;              // PENALTY
        const float result   = 2.0f * (prior - beta * 262144.0f - flt
                                + 2.5066282746310002f * expf(beta) * integral);
        out[0] = result;
        g_unit_ctr = 0;   // reset work-stealing counter for the next call
    }
}

// ---------------------------------------------------------------------------
extern "C" void kernel_launch(void* const* d_in, const int* in_sizes, int n_in,
                              void* d_out, int out_size)
{
    const float* Z    = (const float*)d_in[0];
    const float* beta = (const float*)d_in[1];
    const float* ts   = (const float*)d_in[2];
    const int*   snd  = (const int*)d_in[3];
    const int*   rcv  = (const int*)d_in[4];
    const int*   nds  = (const int*)d_in[5];
    const int*   su   = (const int*)d_in[6];
    const float* cp   = (const float*)d_in[7];
    float* out = (float*)d_out;

    prior_kernel<<<1, 256>>>(Z, nds);
    integral_kernel<<<INT_GRID, 256>>>(Z, su, cp);
    flt_kernel<<<FLT_BLOCKS, 256>>>(Z, ts, snd, rcv, cp);
    final_kernel<<<1, 256>>>(beta, out);
}